// round 2
// baseline (speedup 1.0000x reference)
#include <cuda_runtime.h>

#define NPG   100     // nodes per graph
#define PAD   102     // smem row stride for W1/h1/W2 tiles (conflict-free f32x2)
#define DEG   16
#define BLK   256
#define NGRAPH 512

__device__ __forceinline__ unsigned long long f32x2_fma(unsigned long long a,
                                                        unsigned long long b,
                                                        unsigned long long c) {
    unsigned long long d;
    asm("fma.rn.f32x2 %0, %1, %2, %3;" : "=l"(d) : "l"(a), "l"(b), "l"(c));
    return d;
}
__device__ __forceinline__ unsigned long long f32x2_add(unsigned long long a,
                                                        unsigned long long b) {
    unsigned long long d;
    asm("add.rn.f32x2 %0, %1, %2;" : "=l"(d) : "l"(a), "l"(b));
    return d;
}
__device__ __forceinline__ unsigned long long f32x2_mul(unsigned long long a,
                                                        unsigned long long b) {
    unsigned long long d;
    asm("mul.rn.f32x2 %0, %1, %2;" : "=l"(d) : "l"(a), "l"(b));
    return d;
}
__device__ __forceinline__ float f32x2_hsum(unsigned long long v) {
    float lo = __uint_as_float((unsigned)(v & 0xffffffffull));
    float hi = __uint_as_float((unsigned)(v >> 32));
    return lo + hi;
}
__device__ __forceinline__ unsigned long long f32x2_pack(float lo, float hi) {
    return (unsigned long long)__float_as_uint(lo)
         | ((unsigned long long)__float_as_uint(hi) << 32);
}
__device__ __forceinline__ unsigned long long f32x2_relu(unsigned long long v) {
    float lo = fmaxf(__uint_as_float((unsigned)(v & 0xffffffffull)), 0.f);
    float hi = fmaxf(__uint_as_float((unsigned)(v >> 32)), 0.f);
    return f32x2_pack(lo, hi);
}

// float offsets into dynamic smem
#define OFF_W1   0                       // [100][102]  W1, later h1
#define OFF_P    (OFF_W1 + NPG * PAD)    // [100][100]  P = feat@W1^T, later sT[100][20]
#define OFF_W2   (OFF_P + NPG * 100)     // [20][102]
#define OFF_B1   (OFF_W2 + 20 * PAD)     // [100]
#define OFF_B2   (OFF_B1 + 100)          // [20]
#define OFF_HG   (OFF_B2 + 20)           // [20]
#define OFF_VEC  (OFF_HG + 20)           // [32]
#define OFF_SRC  (OFF_VEC + 32)          // bytes: [1600]
#define SMEM_FLOATS (OFF_SRC + (NPG * DEG + 3) / 4)

__global__ __launch_bounds__(BLK, 2)
void gnn_fused_kernel(const float* __restrict__ feat,
                      const int*   __restrict__ edge_src,
                      const float* __restrict__ self_feat,
                      const float* __restrict__ x3d,
                      const float* __restrict__ W1, const float* __restrict__ b1,
                      const float* __restrict__ W2, const float* __restrict__ b2,
                      const float* __restrict__ Wv2, const float* __restrict__ Wo2,
                      const float* __restrict__ g2,  const float* __restrict__ be2,
                      const float* __restrict__ Wv3, const float* __restrict__ Wo3,
                      const float* __restrict__ g3,  const float* __restrict__ be3,
                      const float* __restrict__ Wf1, const float* __restrict__ bf1,
                      const float* __restrict__ Wf2, const float* __restrict__ bf2,
                      float* __restrict__ out)
{
    extern __shared__ float smem[];
    float* sW1  = smem + OFF_W1;   // W1 tile, overwritten by h1 later
    float* sP   = smem + OFF_P;    // P tile, overwritten by sT later
    float* sW2  = smem + OFF_W2;
    float* sB1  = smem + OFF_B1;
    float* sB2  = smem + OFF_B2;
    float* shg  = smem + OFF_HG;
    float* sVec = smem + OFF_VEC;
    unsigned char* sSrc = (unsigned char*)(smem + OFF_SRC);

    const int g    = blockIdx.x;
    const int tid  = threadIdx.x;
    const int lane = tid & 31;
    const int warp = tid >> 5;

    // ---------------- phase 0: load weights / edges ----------------
    {
        const float4* gw = (const float4*)W1;
        for (int i = tid; i < 100 * 100 / 4; i += BLK) {
            float4 v = gw[i];
            int row = (i * 4) / 100, col = (i * 4) % 100;
            float* d = sW1 + row * PAD + col;
            d[0] = v.x; d[1] = v.y; d[2] = v.z; d[3] = v.w;
        }
        const float4* gw2 = (const float4*)W2;
        for (int i = tid; i < 20 * 100 / 4; i += BLK) {
            float4 v = gw2[i];
            int row = (i * 4) / 100, col = (i * 4) % 100;
            float* d = sW2 + row * PAD + col;
            d[0] = v.x; d[1] = v.y; d[2] = v.z; d[3] = v.w;
        }
        if (tid < 100) sB1[tid] = b1[tid];
        if (tid < 20)  sB2[tid] = b2[tid];
        if (tid < 20)  shg[tid] = 0.f;
        const int* es = edge_src + g * NPG * DEG;
        const int base = g * NPG;
        for (int i = tid; i < NPG * DEG; i += BLK)
            sSrc[i] = (unsigned char)(es[i] - base);
    }
    __syncthreads();

    // ---------------- phase A: P = feat @ W1^T  (A from global/L1, B from smem)
    {
        const int tx = tid & 15, ty = tid >> 4;
        const float* gfeat = feat + (size_t)g * NPG * 100;
        const unsigned long long* pa[7];
        #pragma unroll
        for (int i = 0; i < 7; i++) {
            int r = ty + 16 * i; r = (r > 99) ? 99 : r;
            pa[i] = (const unsigned long long*)(gfeat + r * 100);
        }
        #pragma unroll
        for (int jp = 0; jp < 2; jp++) {
            const int jb = jp * 50;
            const unsigned long long* pb[4];
            #pragma unroll
            for (int k = 0; k < 4; k++) {
                int j = jb + tx + 16 * k; j = (j > 99) ? 99 : j;
                pb[k] = (const unsigned long long*)(sW1 + j * PAD);
            }
            unsigned long long acc[7][4];
            #pragma unroll
            for (int i = 0; i < 7; i++)
                #pragma unroll
                for (int k = 0; k < 4; k++) acc[i][k] = 0ull;

            #pragma unroll 2
            for (int dp = 0; dp < 50; dp++) {
                unsigned long long av[7], bv[4];
                #pragma unroll
                for (int i = 0; i < 7; i++) av[i] = pa[i][dp];
                #pragma unroll
                for (int k = 0; k < 4; k++) bv[k] = pb[k][dp];
                #pragma unroll
                for (int i = 0; i < 7; i++)
                    #pragma unroll
                    for (int k = 0; k < 4; k++)
                        acc[i][k] = f32x2_fma(av[i], bv[k], acc[i][k]);
            }
            #pragma unroll
            for (int i = 0; i < 7; i++) {
                int r = ty + 16 * i;
                if (r > 99) continue;
                #pragma unroll
                for (int k = 0; k < 4; k++) {
                    int j = jb + tx + 16 * k;
                    if (j >= jb + 50) continue;
                    sP[r * 100 + j] = f32x2_hsum(acc[i][k]);
                }
            }
        }
    }
    __syncthreads();

    // ---------------- phase B: h1 = relu(mean_e P[src] + b1) -> over sW1 ----------------
    {
        const unsigned long long scale = f32x2_pack(1.f / DEG, 1.f / DEG);
        const unsigned long long* bb = (const unsigned long long*)sB1;
        const bool lo2 = (lane < 18);   // 50 f32x2 cols: lane + (lane<18 ? lane+32)
        for (int n = warp; n < NPG; n += 8) {
            const unsigned* pw = (const unsigned*)(sSrc + n * DEG);
            unsigned long long a0 = 0ull, a1 = 0ull;
            #pragma unroll
            for (int q = 0; q < 4; q++) {
                unsigned w4 = pw[q];
                #pragma unroll
                for (int b = 0; b < 4; b++) {
                    int s = (w4 >> (8 * b)) & 0xff;
                    const unsigned long long* r = (const unsigned long long*)(sP + s * 100);
                    a0 = f32x2_add(a0, r[lane]);
                    if (lo2) a1 = f32x2_add(a1, r[lane + 32]);
                }
            }
            unsigned long long* o = (unsigned long long*)(sW1 + n * PAD);
            unsigned long long v0 = f32x2_relu(f32x2_add(f32x2_mul(a0, scale), bb[lane]));
            o[lane] = v0;
            if (lo2) {
                unsigned long long v1 = f32x2_relu(f32x2_add(f32x2_mul(a1, scale), bb[lane + 32]));
                o[lane + 32] = v1;
            }
        }
    }
    __syncthreads();

    // ---------------- phase C: sT = h1 @ W2^T -> sP[100][20] ----------------
    {
        const int kk = (lane < 20) ? lane : 19;
        const unsigned long long* pb = (const unsigned long long*)(sW2 + kk * PAD);
        const unsigned long long* pa[13];
        unsigned long long acc[13];
        #pragma unroll
        for (int i = 0; i < 13; i++) {
            int n = warp + 8 * i; n = (n > 99) ? 99 : n;
            pa[i] = (const unsigned long long*)(sW1 + n * PAD);
            acc[i] = 0ull;
        }
        #pragma unroll 2
        for (int dp = 0; dp < 50; dp++) {
            unsigned long long bv = pb[dp];
            #pragma unroll
            for (int i = 0; i < 13; i++)
                acc[i] = f32x2_fma(pa[i][dp], bv, acc[i]);
        }
        __syncthreads();   // all reads of old sP (none) / h1 done; sT overwrites sP
        if (lane < 20) {
            #pragma unroll
            for (int i = 0; i < 13; i++) {
                int n = warp + 8 * i;
                if (n > 99) continue;
                sP[n * 20 + lane] = f32x2_hsum(acc[i]);
            }
        }
    }
    __syncthreads();

    // ---------------- phase D: h2 = relu(mean_e sT[src] + b2); hg = mean_n h2 ----------------
    if (lane < 20) {
        float hgacc = 0.f;
        for (int n = warp; n < NPG; n += 8) {
            const unsigned char* sp = sSrc + n * DEG;
            float a = 0.f;
            #pragma unroll
            for (int e = 0; e < DEG; e++)
                a += sP[sp[e] * 20 + lane];
            float h = a * (1.f / DEG) + sB2[lane];
            hgacc += fmaxf(h, 0.f);
        }
        atomicAdd(&shg[lane], hgacc);
    }
    __syncthreads();

    // ---------------- phase E: tail (warp 0): 2x (V@Wo + LN) + MLP ----------------
    if (warp == 0) {
        float hgk = (lane < 20) ? shg[lane] * (1.f / NPG) : 0.f;

        // v2 = Wv2 @ self_feat[g]   (softmax over length-1 axis == 1; Q irrelevant)
        {
            const float4* xr = (const float4*)(self_feat + (size_t)g * 200);
            const float4* wr = (const float4*)(Wv2 + lane * 200);
            float acc = 0.f;
            #pragma unroll 5
            for (int p = 0; p < 50; p++) {
                float4 a = wr[p], b = xr[p];
                acc += a.x * b.x + a.y * b.y + a.z * b.z + a.w * b.w;
            }
            sVec[lane] = acc;
        }
        __syncwarp();
        float y = 0.f;
        if (lane < 20) {
            const float* wo = Wo2 + lane * 32;
            float z = 0.f;
            #pragma unroll
            for (int j = 0; j < 32; j++) z += wo[j] * sVec[j];
            y = hgk + z;
        }
        float s = y;
        #pragma unroll
        for (int o = 16; o; o >>= 1) s += __shfl_xor_sync(0xffffffffu, s, o);
        float mu = s * (1.f / 20.f);
        float dd = (lane < 20) ? (y - mu) : 0.f;
        float vv = dd * dd;
        #pragma unroll
        for (int o = 16; o; o >>= 1) vv += __shfl_xor_sync(0xffffffffu, vv, o);
        float hg1 = 0.f;
        if (lane < 20)
            hg1 = dd * rsqrtf(vv * (1.f / 20.f) + 1e-5f) * g2[lane] + be2[lane];

        __syncwarp();
        // v3 = Wv3 @ x3d[g]
        {
            const float4* xr = (const float4*)(x3d + (size_t)g * 100);
            const float4* wr = (const float4*)(Wv3 + lane * 100);
            float acc = 0.f;
            #pragma unroll 5
            for (int p = 0; p < 25; p++) {
                float4 a = wr[p], b = xr[p];
                acc += a.x * b.x + a.y * b.y + a.z * b.z + a.w * b.w;
            }
            sVec[lane] = acc;
        }
        __syncwarp();
        float y2 = 0.f;
        if (lane < 20) {
            const float* wo = Wo3 + lane * 32;
            float z = 0.f;
            #pragma unroll
            for (int j = 0; j < 32; j++) z += wo[j] * sVec[j];
            y2 = hg1 + z;
        }
        float s2 = y2;
        #pragma unroll
        for (int o = 16; o; o >>= 1) s2 += __shfl_xor_sync(0xffffffffu, s2, o);
        float mu2 = s2 * (1.f / 20.f);
        float d2 = (lane < 20) ? (y2 - mu2) : 0.f;
        float v2s = d2 * d2;
        #pragma unroll
        for (int o = 16; o; o >>= 1) v2s += __shfl_xor_sync(0xffffffffu, v2s, o);
        float hg2 = 0.f;
        if (lane < 20)
            hg2 = d2 * rsqrtf(v2s * (1.f / 20.f) + 1e-5f) * g3[lane] + be3[lane];

        __syncwarp();
        if (lane < 20) sVec[lane] = hg2;
        __syncwarp();

        float f = 0.f;
        if (lane < 10) {
            const float* wf = Wf1 + lane * 20;
            float a = bf1[lane];
            #pragma unroll
            for (int k = 0; k < 20; k++) a += wf[k] * sVec[k];
            f = fmaxf(a, 0.f) * Wf2[lane];
        }
        #pragma unroll
        for (int o = 16; o; o >>= 1) f += __shfl_xor_sync(0xffffffffu, f, o);
        if (lane == 0) out[g] = f + bf2[0];
    }
}

extern "C" void kernel_launch(void* const* d_in, const int* in_sizes, int n_in,
                              void* d_out, int out_size) {
    const float* feat      = (const float*)d_in[0];
    const int*   edge_src  = (const int*)  d_in[1];
    // d_in[2] = edge_dst: repeat(arange(N), DEG) by construction — implicit
    const float* self_feat = (const float*)d_in[3];
    const float* x3d       = (const float*)d_in[4];
    const float* W1  = (const float*)d_in[5];
    const float* b1  = (const float*)d_in[6];
    const float* W2  = (const float*)d_in[7];
    const float* b2  = (const float*)d_in[8];
    const float* Wv2 = (const float*)d_in[11];
    const float* Wo2 = (const float*)d_in[12];
    const float* g2  = (const float*)d_in[13];
    const float* be2 = (const float*)d_in[14];
    const float* Wv3 = (const float*)d_in[17];
    const float* Wo3 = (const float*)d_in[18];
    const float* g3  = (const float*)d_in[19];
    const float* be3 = (const float*)d_in[20];
    const float* Wf1 = (const float*)d_in[21];
    const float* bf1 = (const float*)d_in[22];
    const float* Wf2 = (const float*)d_in[23];
    const float* bf2 = (const float*)d_in[24];

    const size_t smem_bytes = (size_t)SMEM_FLOATS * sizeof(float);

    cudaFuncSetAttribute(gnn_fused_kernel,
                         cudaFuncAttributeMaxDynamicSharedMemorySize,
                         (int)smem_bytes);

    gnn_fused_kernel<<<NGRAPH, BLK, smem_bytes>>>(
        feat, edge_src, self_feat, x3d,
        W1, b1, W2, b2,
        Wv2, Wo2, g2, be2,
        Wv3, Wo3, g3, be3,
        Wf1, bf1, Wf2, bf2,
        (float*)d_out);
}

// round 4
// speedup vs baseline: 1.3474x; 1.3474x over previous
#include <cuda_runtime.h>
#include <cstdint>

// ============================ common ============================
#define NPG   100
#define PAD   102
#define DEG   16
#define BLK   256
#define NGRAPH 512
#define NNODES (NGRAPH * NPG)

// P = feat @ W1^T, staged between the two kernels
__device__ float P_buf[(size_t)NNODES * 100];

// ====================== kernel 1: tf32 mma.sync GEMM ======================
// C[51200,100] = feat[51200,100] @ W1^T[100,100]
// per CTA: 128 rows; per warp: one m16 strip x 13 n-tiles x 13 k-tiles
#define KP 108      // smem k-stride (floats): g*12+tig mod 32 distinct -> conflict-free
#define NPAD 104    // padded B rows (n up to 103)

__device__ __forceinline__ uint32_t cvt_tf32(float x) {
    uint32_t r;
    asm("cvt.rna.tf32.f32 %0, %1;" : "=r"(r) : "f"(x));
    return r;
}
__device__ __forceinline__ void mma_tf32(float* acc, const uint32_t* a,
                                         uint32_t b0, uint32_t b1) {
    asm volatile("mma.sync.aligned.m16n8k8.row.col.f32.tf32.tf32.f32 "
                 "{%0,%1,%2,%3}, {%4,%5,%6,%7}, {%8,%9}, {%0,%1,%2,%3};"
                 : "+f"(acc[0]), "+f"(acc[1]), "+f"(acc[2]), "+f"(acc[3])
                 : "r"(a[0]), "r"(a[1]), "r"(a[2]), "r"(a[3]),
                   "r"(b0), "r"(b1));
}

#define K1_SMEM (2 * NPAD * KP * sizeof(float))   // 89856 B

__global__ __launch_bounds__(BLK, 2)
void gemm1_kernel(const float* __restrict__ feat, const float* __restrict__ W1)
{
    extern __shared__ uint32_t sm1[];
    uint32_t* Bhi = sm1;                 // [NPAD][KP] tf32 bit patterns
    uint32_t* Blo = sm1 + NPAD * KP;

    const int tid  = threadIdx.x;
    const int warp = tid >> 5;
    const int lane = tid & 31;
    const int g    = lane >> 2;          // groupID
    const int tig  = lane & 3;           // threadID_in_group

    // zero padded region (simplest: zero everything, then overwrite)
    for (int i = tid; i < 2 * NPAD * KP; i += BLK) sm1[i] = 0u;
    __syncthreads();

    // W1 [100 rows(n)][100 cols(k)] -> tf32 hi/lo into smem [n][k]
    {
        const float4* gw = (const float4*)W1;
        for (int i = tid; i < 100 * 100 / 4; i += BLK) {
            float4 v = gw[i];
            int row = (i * 4) / 100, col = (i * 4) % 100;
            uint32_t* dh = Bhi + row * KP + col;
            uint32_t* dl = Blo + row * KP + col;
            float x[4] = { v.x, v.y, v.z, v.w };
            #pragma unroll
            for (int q = 0; q < 4; q++) {
                uint32_t h = cvt_tf32(x[q]);
                dh[q] = h;
                dl[q] = cvt_tf32(x[q] - __uint_as_float(h));
            }
        }
    }
    __syncthreads();

    const int mbase = blockIdx.x * 128 + warp * 16;
    const float* arow0 = feat + (size_t)(mbase + g) * 100;
    const float* arow1 = feat + (size_t)(mbase + 8 + g) * 100;

    float acc[13][4];
    #pragma unroll
    for (int nt = 0; nt < 13; nt++)
        #pragma unroll
        for (int q = 0; q < 4; q++) acc[nt][q] = 0.f;

    #pragma unroll 1
    for (int kt = 0; kt < 13; kt++) {
        const int k0 = kt * 8;
        const int kA = k0 + tig;        // <= 99+? guard
        const int kB = k0 + tig + 4;
        float a0f = (kA < 100) ? __ldg(arow0 + kA) : 0.f;
        float a1f = (kA < 100) ? __ldg(arow1 + kA) : 0.f;
        float a2f = (kB < 100) ? __ldg(arow0 + kB) : 0.f;
        float a3f = (kB < 100) ? __ldg(arow1 + kB) : 0.f;
        uint32_t ah[4], al[4];
        ah[0] = cvt_tf32(a0f); al[0] = cvt_tf32(a0f - __uint_as_float(ah[0]));
        ah[1] = cvt_tf32(a1f); al[1] = cvt_tf32(a1f - __uint_as_float(ah[1]));
        ah[2] = cvt_tf32(a2f); al[2] = cvt_tf32(a2f - __uint_as_float(ah[2]));
        ah[3] = cvt_tf32(a3f); al[3] = cvt_tf32(a3f - __uint_as_float(ah[3]));

        const uint32_t* bh = Bhi + g * KP + k0 + tig;   // row n0+g, col k0+tig
        const uint32_t* bl = Blo + g * KP + k0 + tig;
        #pragma unroll
        for (int nt = 0; nt < 13; nt++) {
            const int roff = nt * 8 * KP;
            uint32_t bh0 = bh[roff], bh1 = bh[roff + 4];
            uint32_t bl0 = bl[roff], bl1 = bl[roff + 4];
            mma_tf32(acc[nt], ah, bh0, bh1);
            mma_tf32(acc[nt], ah, bl0, bl1);
            mma_tf32(acc[nt], al, bh0, bh1);
        }
    }

    // epilogue: c0,c1 -> row mbase+g, cols (n0+2tig, +1); c2,c3 -> row mbase+8+g
    float* crow0 = P_buf + (size_t)(mbase + g) * 100;
    float* crow1 = P_buf + (size_t)(mbase + 8 + g) * 100;
    #pragma unroll
    for (int nt = 0; nt < 13; nt++) {
        int col = nt * 8 + 2 * tig;
        if (col < 100) {
            *(float2*)(crow0 + col) = make_float2(acc[nt][0], acc[nt][1]);
            *(float2*)(crow1 + col) = make_float2(acc[nt][2], acc[nt][3]);
        }
    }
}

// ====================== kernel 2: rest of the net ======================
__device__ __forceinline__ unsigned long long f32x2_fma(unsigned long long a,
                                                        unsigned long long b,
                                                        unsigned long long c) {
    unsigned long long d;
    asm("fma.rn.f32x2 %0, %1, %2, %3;" : "=l"(d) : "l"(a), "l"(b), "l"(c));
    return d;
}
__device__ __forceinline__ unsigned long long f32x2_add(unsigned long long a,
                                                        unsigned long long b) {
    unsigned long long d;
    asm("add.rn.f32x2 %0, %1, %2;" : "=l"(d) : "l"(a), "l"(b));
    return d;
}
__device__ __forceinline__ unsigned long long f32x2_mul(unsigned long long a,
                                                        unsigned long long b) {
    unsigned long long d;
    asm("mul.rn.f32x2 %0, %1, %2;" : "=l"(d) : "l"(a), "l"(b));
    return d;
}
__device__ __forceinline__ float f32x2_hsum(unsigned long long v) {
    return __uint_as_float((unsigned)(v & 0xffffffffull))
         + __uint_as_float((unsigned)(v >> 32));
}
__device__ __forceinline__ unsigned long long f32x2_pack(float lo, float hi) {
    return (unsigned long long)__float_as_uint(lo)
         | ((unsigned long long)__float_as_uint(hi) << 32);
}
__device__ __forceinline__ unsigned long long f32x2_relu(unsigned long long v) {
    float lo = fmaxf(__uint_as_float((unsigned)(v & 0xffffffffull)), 0.f);
    float hi = fmaxf(__uint_as_float((unsigned)(v >> 32)), 0.f);
    return f32x2_pack(lo, hi);
}

#define OFF_H1   0                       // [100][102]  h1
#define OFF_P    (OFF_H1 + NPG * PAD)    // [100][100]  P tile -> later sT[100][20]
#define OFF_W2   (OFF_P + NPG * 100)     // [20][102]
#define OFF_B1   (OFF_W2 + 20 * PAD)     // [100]
#define OFF_B2   (OFF_B1 + 100)          // [20]
#define OFF_HG   (OFF_B2 + 20)           // [20]
#define OFF_VEC  (OFF_HG + 20)           // [32]
#define OFF_SRC  (OFF_VEC + 32)          // bytes [1600]
#define K2_SMEM_FLOATS (OFF_SRC + (NPG * DEG + 3) / 4)

__global__ __launch_bounds__(BLK, 2)
void gnn_rest_kernel(const int*   __restrict__ edge_src,
                     const float* __restrict__ self_feat,
                     const float* __restrict__ x3d,
                     const float* __restrict__ b1,
                     const float* __restrict__ W2, const float* __restrict__ b2,
                     const float* __restrict__ Wv2, const float* __restrict__ Wo2,
                     const float* __restrict__ g2,  const float* __restrict__ be2,
                     const float* __restrict__ Wv3, const float* __restrict__ Wo3,
                     const float* __restrict__ g3,  const float* __restrict__ be3,
                     const float* __restrict__ Wf1, const float* __restrict__ bf1,
                     const float* __restrict__ Wf2, const float* __restrict__ bf2,
                     float* __restrict__ out)
{
    extern __shared__ float smem[];
    float* sH1  = smem + OFF_H1;
    float* sP   = smem + OFF_P;
    float* sW2  = smem + OFF_W2;
    float* sB1  = smem + OFF_B1;
    float* sB2  = smem + OFF_B2;
    float* shg  = smem + OFF_HG;
    float* sVec = smem + OFF_VEC;
    unsigned char* sSrc = (unsigned char*)(smem + OFF_SRC);

    const int g    = blockIdx.x;
    const int tid  = threadIdx.x;
    const int lane = tid & 31;
    const int warp = tid >> 5;

    // ---- phase 0: load P tile, W2, biases, edges ----
    {
        const float4* gp = (const float4*)(P_buf + (size_t)g * NPG * 100);
        #pragma unroll 4
        for (int i = tid; i < NPG * 100 / 4; i += BLK)
            ((float4*)sP)[i] = gp[i];
        const float4* gw2 = (const float4*)W2;
        for (int i = tid; i < 20 * 100 / 4; i += BLK) {
            float4 v = gw2[i];
            int row = (i * 4) / 100, col = (i * 4) % 100;
            float* d = sW2 + row * PAD + col;
            d[0] = v.x; d[1] = v.y; d[2] = v.z; d[3] = v.w;
        }
        if (tid < 100) sB1[tid] = b1[tid];
        if (tid < 20)  sB2[tid] = b2[tid];
        if (tid < 20)  shg[tid] = 0.f;
        const int* es = edge_src + g * NPG * DEG;
        const int base = g * NPG;
        for (int i = tid; i < NPG * DEG; i += BLK)
            sSrc[i] = (unsigned char)(es[i] - base);
    }
    __syncthreads();

    // ---- phase B: h1 = relu(mean_e P[src] + b1) -> sH1 ----
    {
        const unsigned long long scale = f32x2_pack(1.f / DEG, 1.f / DEG);
        const unsigned long long* bb = (const unsigned long long*)sB1;
        const bool lo2 = (lane < 18);
        for (int n = warp; n < NPG; n += 8) {
            const unsigned* pw = (const unsigned*)(sSrc + n * DEG);
            unsigned long long a0 = 0ull, a1 = 0ull;
            #pragma unroll
            for (int q = 0; q < 4; q++) {
                unsigned w4 = pw[q];
                #pragma unroll
                for (int b = 0; b < 4; b++) {
                    int s = (w4 >> (8 * b)) & 0xff;
                    const unsigned long long* r = (const unsigned long long*)(sP + s * 100);
                    a0 = f32x2_add(a0, r[lane]);
                    if (lo2) a1 = f32x2_add(a1, r[lane + 32]);
                }
            }
            unsigned long long* o = (unsigned long long*)(sH1 + n * PAD);
            o[lane] = f32x2_relu(f32x2_add(f32x2_mul(a0, scale), bb[lane]));
            if (lo2)
                o[lane + 32] = f32x2_relu(f32x2_add(f32x2_mul(a1, scale), bb[lane + 32]));
        }
    }
    __syncthreads();

    // ---- phase C: sT = h1 @ W2^T -> sP[100][20] ----
    {
        const int kk = (lane < 20) ? lane : 19;
        const unsigned long long* pb = (const unsigned long long*)(sW2 + kk * PAD);
        const unsigned long long* pa[13];
        unsigned long long acc[13];
        #pragma unroll
        for (int i = 0; i < 13; i++) {
            int n = warp + 8 * i; n = (n > 99) ? 99 : n;
            pa[i] = (const unsigned long long*)(sH1 + n * PAD);
            acc[i] = 0ull;
        }
        #pragma unroll 2
        for (int dp = 0; dp < 50; dp++) {
            unsigned long long bv = pb[dp];
            #pragma unroll
            for (int i = 0; i < 13; i++)
                acc[i] = f32x2_fma(pa[i][dp], bv, acc[i]);
        }
        __syncthreads();   // old sP reads done; sT overwrites it
        if (lane < 20) {
            #pragma unroll
            for (int i = 0; i < 13; i++) {
                int n = warp + 8 * i;
                if (n > 99) continue;
                sP[n * 20 + lane] = f32x2_hsum(acc[i]);
            }
        }
    }
    __syncthreads();

    // ---- phase D: h2 = relu(mean_e sT[src] + b2); hg = mean_n h2 ----
    if (lane < 20) {
        float hgacc = 0.f;
        for (int n = warp; n < NPG; n += 8) {
            const unsigned char* sp = sSrc + n * DEG;
            float a = 0.f;
            #pragma unroll
            for (int e = 0; e < DEG; e++)
                a += sP[sp[e] * 20 + lane];
            float h = a * (1.f / DEG) + sB2[lane];
            hgacc += fmaxf(h, 0.f);
        }
        atomicAdd(&shg[lane], hgacc);
    }
    __syncthreads();

    // ---- phase E: tail (warp 0) ----
    if (warp == 0) {
        float hgk = (lane < 20) ? shg[lane] * (1.f / NPG) : 0.f;

        {
            const float4* xr = (const float4*)(self_feat + (size_t)g * 200);
            const float4* wr = (const float4*)(Wv2 + lane * 200);
            float acc = 0.f;
            #pragma unroll 5
            for (int p = 0; p < 50; p++) {
                float4 a = wr[p], b = xr[p];
                acc += a.x * b.x + a.y * b.y + a.z * b.z + a.w * b.w;
            }
            sVec[lane] = acc;
        }
        __syncwarp();
        float y = 0.f;
        if (lane < 20) {
            const float* wo = Wo2 + lane * 32;
            float z = 0.f;
            #pragma unroll
            for (int j = 0; j < 32; j++) z += wo[j] * sVec[j];
            y = hgk + z;
        }
        float s = y;
        #pragma unroll
        for (int o = 16; o; o >>= 1) s += __shfl_xor_sync(0xffffffffu, s, o);
        float mu = s * (1.f / 20.f);
        float dd = (lane < 20) ? (y - mu) : 0.f;
        float vv = dd * dd;
        #pragma unroll
        for (int o = 16; o; o >>= 1) vv += __shfl_xor_sync(0xffffffffu, vv, o);
        float hg1 = 0.f;
        if (lane < 20)
            hg1 = dd * rsqrtf(vv * (1.f / 20.f) + 1e-5f) * g2[lane] + be2[lane];

        __syncwarp();
        {
            const float4* xr = (const float4*)(x3d + (size_t)g * 100);
            const float4* wr = (const float4*)(Wv3 + lane * 100);
            float acc = 0.f;
            #pragma unroll 5
            for (int p = 0; p < 25; p++) {
                float4 a = wr[p], b = xr[p];
                acc += a.x * b.x + a.y * b.y + a.z * b.z + a.w * b.w;
            }
            sVec[lane] = acc;
        }
        __syncwarp();
        float y2 = 0.f;
        if (lane < 20) {
            const float* wo = Wo3 + lane * 32;
            float z = 0.f;
            #pragma unroll
            for (int j = 0; j < 32; j++) z += wo[j] * sVec[j];
            y2 = hg1 + z;
        }
        float s2 = y2;
        #pragma unroll
        for (int o = 16; o; o >>= 1) s2 += __shfl_xor_sync(0xffffffffu, s2, o);
        float mu2 = s2 * (1.f / 20.f);
        float d2 = (lane < 20) ? (y2 - mu2) : 0.f;
        float v2s = d2 * d2;
        #pragma unroll
        for (int o = 16; o; o >>= 1) v2s += __shfl_xor_sync(0xffffffffu, v2s, o);
        float hg2 = 0.f;
        if (lane < 20)
            hg2 = d2 * rsqrtf(v2s * (1.f / 20.f) + 1e-5f) * g3[lane] + be3[lane];

        __syncwarp();
        if (lane < 20) sVec[lane] = hg2;
        __syncwarp();

        float f = 0.f;
        if (lane < 10) {
            const float* wf = Wf1 + lane * 20;
            float a = bf1[lane];
            #pragma unroll
            for (int k = 0; k < 20; k++) a += wf[k] * sVec[k];
            f = fmaxf(a, 0.f) * Wf2[lane];
        }
        #pragma unroll
        for (int o = 16; o; o >>= 1) f += __shfl_xor_sync(0xffffffffu, f, o);
        if (lane == 0) out[g] = f + bf2[0];
    }
}

// ============================ launch ============================
extern "C" void kernel_launch(void* const* d_in, const int* in_sizes, int n_in,
                              void* d_out, int out_size) {
    const float* feat      = (const float*)d_in[0];
    const int*   edge_src  = (const int*)  d_in[1];
    // d_in[2] = edge_dst: repeat(arange(N), DEG) by construction — implicit
    const float* self_feat = (const float*)d_in[3];
    const float* x3d       = (const float*)d_in[4];
    const float* W1  = (const float*)d_in[5];
    const float* b1  = (const float*)d_in[6];
    const float* W2  = (const float*)d_in[7];
    const float* b2  = (const float*)d_in[8];
    const float* Wv2 = (const float*)d_in[11];
    const float* Wo2 = (const float*)d_in[12];
    const float* g2  = (const float*)d_in[13];
    const float* be2 = (const float*)d_in[14];
    const float* Wv3 = (const float*)d_in[17];
    const float* Wo3 = (const float*)d_in[18];
    const float* g3  = (const float*)d_in[19];
    const float* be3 = (const float*)d_in[20];
    const float* Wf1 = (const float*)d_in[21];
    const float* bf1 = (const float*)d_in[22];
    const float* Wf2 = (const float*)d_in[23];
    const float* bf2 = (const float*)d_in[24];

    cudaFuncSetAttribute(gemm1_kernel,
                         cudaFuncAttributeMaxDynamicSharedMemorySize,
                         (int)K1_SMEM);
    gemm1_kernel<<<NNODES / 128, BLK, K1_SMEM>>>(feat, W1);

    const size_t k2_smem = (size_t)K2_SMEM_FLOATS * sizeof(float);
    cudaFuncSetAttribute(gnn_rest_kernel,
                         cudaFuncAttributeMaxDynamicSharedMemorySize,
                         (int)k2_smem);
    gnn_rest_kernel<<<NGRAPH, BLK, k2_smem>>>(
        edge_src, self_feat, x3d,
        b1, W2, b2,
        Wv2, Wo2, g2, be2,
        Wv3, Wo3, g3, be3,
        Wf1, bf1, Wf2, bf2,
        (float*)d_out);
}